// round 2
// baseline (speedup 1.0000x reference)
#include <cuda_runtime.h>
#include <cstdint>

// ---------------------------------------------------------------------------
// RNG mapping hypothesis for jax.random.bernoulli(jax.random.key(42), 0.1, shape)
//   MODE 1: threefry_partitionable (JAX >= 0.4.36 default):
//           bits[i] = x0 ^ x1 of threefry2x32(key=(0,42), ctr=(0, i))
//   MODE 2: legacy (partitionable=False): counter iota split in halves
//   MODE 3: partitionable but taking x0 only
// ---------------------------------------------------------------------------
#define RNG_MODE 1

static constexpr int Bc = 4, Hc = 16, Sc = 2048, Dc = 64;
static constexpr int QT = 64, KT = 64;
static constexpr int NTHREADS = 256;
// sQ [64][64] + sKt [64][68] + sV [64][64]; sP aliases sKt
static constexpr int SMEM_FLOATS = 64 * 64 + 64 * 68 + 64 * 64;

__device__ __forceinline__ void threefry2x32(uint32_t c0, uint32_t c1,
                                             uint32_t& o0, uint32_t& o1)
{
    const uint32_t K0 = 0u;
    const uint32_t K1 = 42u;
    const uint32_t K2 = 0x1BD11BDAu ^ K0 ^ K1;
    uint32_t x0 = c0 + K0;
    uint32_t x1 = c1 + K1;
#define TF_R(r) { x0 += x1; x1 = __funnelshift_l(x1, x1, (r)); x1 ^= x0; }
    TF_R(13) TF_R(15) TF_R(26) TF_R(6)
    x0 += K1; x1 += K2 + 1u;
    TF_R(17) TF_R(29) TF_R(16) TF_R(24)
    x0 += K2; x1 += K0 + 2u;
    TF_R(13) TF_R(15) TF_R(26) TF_R(6)
    x0 += K0; x1 += K1 + 3u;
    TF_R(17) TF_R(29) TF_R(16) TF_R(24)
    x0 += K1; x1 += K2 + 4u;
    TF_R(13) TF_R(15) TF_R(26) TF_R(6)
    x0 += K2; x1 += K0 + 5u;
#undef TF_R
    o0 = x0; o1 = x1;
}

// keep = uniform(bits) < float32(0.1)  <=>  (bits >> 9) < 838861
__device__ __forceinline__ bool keep_mask(uint32_t bh, uint32_t gq, uint32_t gk)
{
    uint32_t i = (bh << 22) | (gq << 11) | gk;   // linear index, < 2^28
    uint32_t b0, b1, bits;
#if RNG_MODE == 1
    threefry2x32(0u, i, b0, b1);
    bits = b0 ^ b1;
#elif RNG_MODE == 2
    const uint32_t HALF = 1u << 27;
    if (bh < 32u) { threefry2x32(i, i + HALF, b0, b1); bits = b0; }
    else          { threefry2x32(i - HALF, i, b0, b1); bits = b1; }
#else
    threefry2x32(0u, i, b0, b1);
    bits = b0;
#endif
    return (bits >> 9) < 838861u;
}

__device__ __forceinline__ float f4c(const float4 v, int t)
{
    return t == 0 ? v.x : t == 1 ? v.y : t == 2 ? v.z : v.w;
}

__global__ void __launch_bounds__(NTHREADS, 2)
attn_kernel(const float* __restrict__ gq, const float* __restrict__ gk,
            const float* __restrict__ gv, float* __restrict__ gout)
{
    extern __shared__ float smem[];
    float* sQ  = smem;                        // [64][64] natural, pre-scaled by 8
    float* sKt = smem + 64 * 64;              // [64(d)][stride 68] transposed
    float* sV  = smem + 64 * 64 + 64 * 68;    // [64][64]
    float* sP  = sKt;                         // alias (K dead after S-GEMM)

    const int tid = threadIdx.x;
    const int ty = tid >> 4;      // 0..15 -> owns 4 q rows
    const int tx = tid & 15;      // 0..15 -> owns 4 cols
    const uint32_t bh = blockIdx.y;
    const int q0 = blockIdx.x * QT;

    const float* qb  = gq + ((size_t)bh * Sc + q0) * Dc;
    const float* kb0 = gk + (size_t)bh * Sc * Dc;
    const float* vb0 = gv + (size_t)bh * Sc * Dc;

    // --- load Q tile (scaled by sqrt(D)=8: reference divides by D**-0.5) ---
#pragma unroll
    for (int it = 0; it < 4; ++it) {
        int idx = tid + it * NTHREADS;
        int row = idx >> 4;
        int c4  = (idx & 15) << 2;
        float4 vq = *(const float4*)(qb + (row << 6) + c4);
        vq.x *= 8.f; vq.y *= 8.f; vq.z *= 8.f; vq.w *= 8.f;
        *(float4*)&sQ[(row << 6) + c4] = vq;
    }

    float o[4][4];
    float m[4], l[4];
#pragma unroll
    for (int r = 0; r < 4; ++r) {
        m[r] = -1e30f; l[r] = 0.f;
#pragma unroll
        for (int j = 0; j < 4; ++j) o[r][j] = 0.f;
    }

    for (int kt = 0; kt < Sc / KT; ++kt) {
        __syncthreads();   // prior iter's sP/sV reads complete before overwrite

        // --- load K tile transposed (sKt[d][k]) and V tile (sV[k][d]) ---
        const float* kb = kb0 + (size_t)kt * KT * Dc;
        const float* vb = vb0 + (size_t)kt * KT * Dc;
#pragma unroll
        for (int it = 0; it < 4; ++it) {
            int idx = tid + it * NTHREADS;
            int row = idx >> 4;
            int c4  = (idx & 15) << 2;
            float4 vk = *(const float4*)(kb + (row << 6) + c4);
            sKt[(c4 + 0) * 68 + row] = vk.x;
            sKt[(c4 + 1) * 68 + row] = vk.y;
            sKt[(c4 + 2) * 68 + row] = vk.z;
            sKt[(c4 + 3) * 68 + row] = vk.w;
            float4 vv = *(const float4*)(vb + (row << 6) + c4);
            *(float4*)&sV[(row << 6) + c4] = vv;
        }
        __syncthreads();

        // --- S = (8*Q) K^T : 4x4 register tile per thread ---
        float c[4][4];
#pragma unroll
        for (int r = 0; r < 4; ++r)
#pragma unroll
            for (int j = 0; j < 4; ++j) c[r][j] = 0.f;

#pragma unroll 4
        for (int d4 = 0; d4 < 64; d4 += 4) {
            float4 a[4];
#pragma unroll
            for (int r = 0; r < 4; ++r)
                a[r] = *(const float4*)&sQ[(((ty << 2) + r) << 6) + d4];
#pragma unroll
            for (int t = 0; t < 4; ++t) {
                float4 b = *(const float4*)&sKt[(d4 + t) * 68 + (tx << 2)];
#pragma unroll
                for (int r = 0; r < 4; ++r) {
                    float av = f4c(a[r], t);
                    c[r][0] = fmaf(av, b.x, c[r][0]);
                    c[r][1] = fmaf(av, b.y, c[r][1]);
                    c[r][2] = fmaf(av, b.z, c[r][2]);
                    c[r][3] = fmaf(av, b.w, c[r][3]);
                }
            }
        }

        // --- online softmax update (per 4 owned rows; reduce over 16 lanes) ---
        float alpha[4];
        float sig_local = 0.f;
#pragma unroll
        for (int r = 0; r < 4; ++r) {
            float tm = fmaxf(fmaxf(c[r][0], c[r][1]), fmaxf(c[r][2], c[r][3]));
#pragma unroll
            for (int s = 1; s < 16; s <<= 1)
                tm = fmaxf(tm, __shfl_xor_sync(0xffffffffu, tm, s));
            float mn = fmaxf(m[r], tm);
            alpha[r] = __expf(m[r] - mn);
            float rs = 0.f;
#pragma unroll
            for (int j = 0; j < 4; ++j) {
                c[r][j] = __expf(c[r][j] - mn);
                rs += c[r][j];
            }
#pragma unroll
            for (int s = 1; s < 16; s <<= 1)
                rs += __shfl_xor_sync(0xffffffffu, rs, s);
            l[r] = l[r] * alpha[r] + rs;
            m[r] = mn;
#pragma unroll
            for (int j = 0; j < 4; ++j) o[r][j] *= alpha[r];
            sig_local = fmaxf(sig_local,
                              fmaxf(fmaxf(c[r][0], c[r][1]), fmaxf(c[r][2], c[r][3])));
        }

        // --- block vote: any probability above negligibility threshold? ---
        int anysig = __syncthreads_or(sig_local > 1e-12f);

        if (anysig) {
            // dropout mask (threefry) only for non-negligible entries,
            // masked & scaled P -> smem (overwrites sKt)
#pragma unroll
            for (int r = 0; r < 4; ++r) {
                uint32_t gqr = (uint32_t)(q0 + (ty << 2) + r);
                float pv[4];
#pragma unroll
                for (int j = 0; j < 4; ++j) {
                    float p = c[r][j];
                    float op = 0.f;
                    if (p > 1e-12f) {
                        uint32_t gkc = (uint32_t)(kt * KT + (tx << 2) + j);
                        if (keep_mask(bh, gqr, gkc)) op = p * 10.f;
                    }
                    pv[j] = op;
                }
                *(float4*)&sP[(((ty << 2) + r) << 6) + (tx << 2)] =
                    make_float4(pv[0], pv[1], pv[2], pv[3]);
            }
            __syncthreads();

            // --- O += P V ---
#pragma unroll 4
            for (int k4 = 0; k4 < 64; k4 += 4) {
                float4 a[4];
#pragma unroll
                for (int r = 0; r < 4; ++r)
                    a[r] = *(const float4*)&sP[(((ty << 2) + r) << 6) + k4];
#pragma unroll
                for (int t = 0; t < 4; ++t) {
                    float4 b = *(const float4*)&sV[((k4 + t) << 6) + (tx << 2)];
#pragma unroll
                    for (int r = 0; r < 4; ++r) {
                        float av = f4c(a[r], t);
                        o[r][0] = fmaf(av, b.x, o[r][0]);
                        o[r][1] = fmaf(av, b.y, o[r][1]);
                        o[r][2] = fmaf(av, b.z, o[r][2]);
                        o[r][3] = fmaf(av, b.w, o[r][3]);
                    }
                }
            }
        }
    }

    // --- epilogue: normalize by l and store ---
    float* ob = gout + ((size_t)bh * Sc + q0) * Dc;
#pragma unroll
    for (int r = 0; r < 4; ++r) {
        float il = 1.0f / l[r];
        float4 st = make_float4(o[r][0] * il, o[r][1] * il,
                                o[r][2] * il, o[r][3] * il);
        *(float4*)&ob[(((ty << 2) + r) << 6) + (tx << 2)] = st;
    }
}

extern "C" void kernel_launch(void* const* d_in, const int* in_sizes, int n_in,
                              void* d_out, int out_size)
{
    (void)in_sizes; (void)n_in; (void)out_size;
    const float* q = (const float*)d_in[0];
    const float* k = (const float*)d_in[1];
    const float* v = (const float*)d_in[2];
    float* o = (float*)d_out;

    size_t smem = SMEM_FLOATS * sizeof(float);   // 50176 bytes
    cudaFuncSetAttribute(attn_kernel,
                         cudaFuncAttributeMaxDynamicSharedMemorySize, (int)smem);
    dim3 grid(Sc / QT, Bc * Hc);
    attn_kernel<<<grid, NTHREADS, smem>>>(q, k, v, o);
}